// round 1
// baseline (speedup 1.0000x reference)
#include <cuda_runtime.h>
#include <math.h>

#define Bq 512
#define Wq 40
#define Vq 12000
#define Eq 512
#define Hq 512
#define G4 2048   // 4*H

// ---------------- scratch (device globals; no allocation) ----------------
__device__ float g_emb[Bq * Wq * Eq];             // 41.9 MB
__device__ float g_xg[2 * Bq * Wq * G4];          // 335 MB (per-dir input projections, reused per layer)
__device__ float g_hseq[Bq * Wq * 2 * Hq];        // 84 MB  (layer output sequence, reused)
__device__ float g_gates[2 * Bq * G4];            // 8.4 MB (recurrent GEMM result per step)
__device__ float g_h[2 * Bq * Hq];
__device__ float g_c[2 * Bq * Hq];

__device__ __forceinline__ float sigf(float x) { return 1.0f / (1.0f + expf(-x)); }

// ---------------- embedding: emb[b,w,e] = tanh(table[v][e]) ----------------
__global__ void embed_kernel(const int* __restrict__ ques, const float* __restrict__ lut) {
    int idx = blockIdx.x * blockDim.x + threadIdx.x;
    if (idx >= Bq * Wq * Eq) return;
    int e = idx & (Eq - 1);
    int bw = idx >> 9;          // / Eq
    int v = ques[bw];
    float val = 0.0f;
    if (v > 0) val = tanhf(lut[(size_t)e * Vq + (v - 1)]);
    g_emb[idx] = val;
}

// ---------------- generic NT SGEMM: C[dir] = A[dir] (MxK) * Bw[dir](NxK)^T (+ bias) ----
// lda = K, ldb = K, ldc = N. 128x128x16 tiles, 256 threads, 8x8 micro-tile.
template <int HAS_BIAS>
__global__ __launch_bounds__(256) void sgemm_nt(
    const float* __restrict__ A, size_t aDirStride,
    const float* __restrict__ Bw, size_t bDirStride,
    const float* __restrict__ bias,           // layout (2, 2, G4): add bias[d][0][n]+bias[d][1][n]
    float* __restrict__ C, size_t cDirStride,
    int M, int N, int K)
{
    const int BK = 16;
    __shared__ float As[BK][128 + 4];
    __shared__ float Bs[BK][128 + 4];

    int dir = blockIdx.z;
    A  += (size_t)dir * aDirStride;
    Bw += (size_t)dir * bDirStride;
    C  += (size_t)dir * cDirStride;

    int m0 = blockIdx.y * 128;
    int n0 = blockIdx.x * 128;
    int tid = threadIdx.x;

    int lr = tid >> 2;            // 0..63 (row within tile, +64 for second half)
    int lk = (tid & 3) * 4;       // 0,4,8,12

    int ty = tid >> 4;            // 0..15 -> row group
    int tx = tid & 15;            // 0..15 -> col group

    float acc[8][8];
#pragma unroll
    for (int i = 0; i < 8; i++)
#pragma unroll
        for (int j = 0; j < 8; j++) acc[i][j] = 0.0f;

    for (int k0 = 0; k0 < K; k0 += BK) {
        float4 a0 = *(const float4*)(A + (size_t)(m0 + lr) * K + k0 + lk);
        float4 a1 = *(const float4*)(A + (size_t)(m0 + lr + 64) * K + k0 + lk);
        float4 b0 = *(const float4*)(Bw + (size_t)(n0 + lr) * K + k0 + lk);
        float4 b1 = *(const float4*)(Bw + (size_t)(n0 + lr + 64) * K + k0 + lk);
        __syncthreads();
        As[lk + 0][lr] = a0.x; As[lk + 1][lr] = a0.y; As[lk + 2][lr] = a0.z; As[lk + 3][lr] = a0.w;
        As[lk + 0][lr + 64] = a1.x; As[lk + 1][lr + 64] = a1.y; As[lk + 2][lr + 64] = a1.z; As[lk + 3][lr + 64] = a1.w;
        Bs[lk + 0][lr] = b0.x; Bs[lk + 1][lr] = b0.y; Bs[lk + 2][lr] = b0.z; Bs[lk + 3][lr] = b0.w;
        Bs[lk + 0][lr + 64] = b1.x; Bs[lk + 1][lr + 64] = b1.y; Bs[lk + 2][lr + 64] = b1.z; Bs[lk + 3][lr + 64] = b1.w;
        __syncthreads();
#pragma unroll
        for (int kk = 0; kk < BK; kk++) {
            float4 av0 = *(const float4*)&As[kk][ty * 8];
            float4 av1 = *(const float4*)&As[kk][ty * 8 + 4];
            float4 bv0 = *(const float4*)&Bs[kk][tx * 8];
            float4 bv1 = *(const float4*)&Bs[kk][tx * 8 + 4];
            float a[8] = {av0.x, av0.y, av0.z, av0.w, av1.x, av1.y, av1.z, av1.w};
            float b[8] = {bv0.x, bv0.y, bv0.z, bv0.w, bv1.x, bv1.y, bv1.z, bv1.w};
#pragma unroll
            for (int i = 0; i < 8; i++)
#pragma unroll
                for (int j = 0; j < 8; j++) acc[i][j] += a[i] * b[j];
        }
    }

    const float* bp = bias + (size_t)dir * 2 * G4;
#pragma unroll
    for (int i = 0; i < 8; i++) {
        int m = m0 + ty * 8 + i;
        float* crow = C + (size_t)m * N + n0 + tx * 8;
#pragma unroll
        for (int j = 0; j < 8; j += 4) {
            float4 v;
            v.x = acc[i][j + 0]; v.y = acc[i][j + 1]; v.z = acc[i][j + 2]; v.w = acc[i][j + 3];
            if (HAS_BIAS) {
                int n = n0 + tx * 8 + j;
                v.x += bp[n + 0] + bp[G4 + n + 0];
                v.y += bp[n + 1] + bp[G4 + n + 1];
                v.z += bp[n + 2] + bp[G4 + n + 2];
                v.w += bp[n + 3] + bp[G4 + n + 3];
            }
            *(float4*)(crow + j) = v;
        }
    }
}

// ---------------- fused LSTM gate update (one timestep, both dirs) ----------------
__global__ void lstm_step_kernel(const float* __restrict__ xg, const float* __restrict__ gates,
                                 float* __restrict__ hseq, int step, int first)
{
    int idx = blockIdx.x * blockDim.x + threadIdx.x;
    if (idx >= 2 * Bq * Hq) return;
    int dir = idx / (Bq * Hq);
    int r = idx - dir * (Bq * Hq);
    int b = r >> 9;            // / Hq
    int h = r & (Hq - 1);
    int t = dir ? (Wq - 1 - step) : step;

    const float* xp = xg + (size_t)dir * Bq * Wq * G4 + ((size_t)b * Wq + t) * G4;
    float gi = xp[h];
    float gf = xp[Hq + h];
    float gg = xp[2 * Hq + h];
    float go = xp[3 * Hq + h];
    if (!first) {
        const float* gp = gates + (size_t)dir * Bq * G4 + (size_t)b * G4;
        gi += gp[h]; gf += gp[Hq + h]; gg += gp[2 * Hq + h]; go += gp[3 * Hq + h];
    }
    float cprev = first ? 0.0f : g_c[idx];
    float c = sigf(gf) * cprev + sigf(gi) * tanhf(gg);
    float hn = sigf(go) * tanhf(c);
    g_c[idx] = c;
    g_h[idx] = hn;
    hseq[((size_t)b * Wq + t) * (2 * Hq) + dir * Hq + h] = hn;
}

// ---------------- final gather at t = len-1 ----------------
__global__ void gather_kernel(const int* __restrict__ qlen, float* __restrict__ out) {
    int idx = blockIdx.x * blockDim.x + threadIdx.x;
    if (idx >= Bq * 2 * Hq) return;
    int b = idx / (2 * Hq);
    int j = idx - b * (2 * Hq);
    int t = qlen[b] - 1;
    out[idx] = g_hseq[((size_t)b * Wq + t) * (2 * Hq) + j];
}

// ---------------- launch ----------------
extern "C" void kernel_launch(void* const* d_in, const int* in_sizes, int n_in,
                              void* d_out, int out_size)
{
    const int*   ques = (const int*)d_in[0];
    const int*   qlen = (const int*)d_in[1];
    const float* lut  = (const float*)d_in[2];
    const float* wih0 = (const float*)d_in[3];
    const float* whh0 = (const float*)d_in[4];
    const float* b0   = (const float*)d_in[5];
    const float* wih1 = (const float*)d_in[6];
    const float* whh1 = (const float*)d_in[7];
    const float* b1   = (const float*)d_in[8];
    float* out = (float*)d_out;

    float *emb, *xg, *hseq, *gates, *hbuf;
    cudaGetSymbolAddress((void**)&emb,   g_emb);
    cudaGetSymbolAddress((void**)&xg,    g_xg);
    cudaGetSymbolAddress((void**)&hseq,  g_hseq);
    cudaGetSymbolAddress((void**)&gates, g_gates);
    cudaGetSymbolAddress((void**)&hbuf,  g_h);

    // 1) embedding
    embed_kernel<<<(Bq * Wq * Eq + 255) / 256, 256>>>(ques, lut);

    // 2) layer-0 input projection: xg[d] = emb @ wih0[d]^T + b0[d][0] + b0[d][1]
    {
        dim3 grid(G4 / 128, (Bq * Wq) / 128, 2);
        sgemm_nt<1><<<grid, 256>>>(emb, 0,
                                   wih0, (size_t)G4 * Eq,
                                   b0,
                                   xg, (size_t)Bq * Wq * G4,
                                   Bq * Wq, G4, Eq);
    }

    // 3) layer-0 recurrence
    for (int step = 0; step < Wq; step++) {
        if (step > 0) {
            dim3 grid(G4 / 128, Bq / 128, 2);
            sgemm_nt<0><<<grid, 256>>>(hbuf, (size_t)Bq * Hq,
                                       whh0, (size_t)G4 * Hq,
                                       b0 /*unused*/,
                                       gates, (size_t)Bq * G4,
                                       Bq, G4, Hq);
        }
        lstm_step_kernel<<<(2 * Bq * Hq + 255) / 256, 256>>>(xg, gates, hseq, step, step == 0);
    }

    // 4) layer-1 input projection: xg[d] = hseq @ wih1[d]^T + b1[d][0] + b1[d][1]  (K = 2H)
    {
        dim3 grid(G4 / 128, (Bq * Wq) / 128, 2);
        sgemm_nt<1><<<grid, 256>>>(hseq, 0,
                                   wih1, (size_t)G4 * 2 * Hq,
                                   b1,
                                   xg, (size_t)Bq * Wq * G4,
                                   Bq * Wq, G4, 2 * Hq);
    }

    // 5) layer-1 recurrence (writes back into g_hseq; input already consumed into xg)
    for (int step = 0; step < Wq; step++) {
        if (step > 0) {
            dim3 grid(G4 / 128, Bq / 128, 2);
            sgemm_nt<0><<<grid, 256>>>(hbuf, (size_t)Bq * Hq,
                                       whh1, (size_t)G4 * Hq,
                                       b1 /*unused*/,
                                       gates, (size_t)Bq * G4,
                                       Bq, G4, Hq);
        }
        lstm_step_kernel<<<(2 * Bq * Hq + 255) / 256, 256>>>(xg, gates, hseq, step, step == 0);
    }

    // 6) gather h at t = ques_len - 1
    gather_kernel<<<(Bq * 2 * Hq + 255) / 256, 256>>>(qlen, out);
}

// round 2
// speedup vs baseline: 1.8933x; 1.8933x over previous
#include <cuda_runtime.h>
#include <math.h>
#include <stdint.h>

#define Bq 512
#define Wq 40
#define Vq 12000
#define Eq 512
#define Hq 512
#define G4 2048   // 4*H

// ---------------- scratch (device globals; no allocation) ----------------
__device__ float g_table[(size_t)Vq * Eq];        // 24.6 MB  tanh(lut^T)
__device__ float g_emb[Bq * Wq * Eq];             // 41.9 MB
__device__ float g_xg[2 * Bq * Wq * G4];          // 335 MB
__device__ float g_hseq[Bq * Wq * 2 * Hq];        // 84 MB
__device__ float g_gates[2 * Bq * G4];            // 8.4 MB
__device__ float g_h[2 * Bq * Hq];
__device__ float g_c[2 * Bq * Hq];

__device__ __forceinline__ float sigf(float x) { return 1.0f / (1.0f + expf(-x)); }

__device__ __forceinline__ uint32_t f2tf32(float x) {
    uint32_t r;
    asm("cvt.rna.tf32.f32 %0, %1;" : "=r"(r) : "f"(x));
    return r;
}

// ---------------- tanh + transpose of lookup table: g_table[v][e] = tanh(lut[e][v]) ----
__global__ void tanh_transpose_kernel(const float* __restrict__ lut) {
    __shared__ float tile[32][33];
    int v0 = blockIdx.x * 32;
    int e0 = blockIdx.y * 32;
    int tx = threadIdx.x, ty = threadIdx.y;   // block (32, 8)
#pragma unroll
    for (int i = ty; i < 32; i += 8) {
        int e = e0 + i, v = v0 + tx;
        tile[i][tx] = (v < Vq) ? lut[(size_t)e * Vq + v] : 0.0f;
    }
    __syncthreads();
#pragma unroll
    for (int i = ty; i < 32; i += 8) {
        int v = v0 + i, e = e0 + tx;
        if (v < Vq) g_table[(size_t)v * Eq + e] = tanhf(tile[tx][i]);
    }
}

// ---------------- embedding gather (coalesced both sides) ----------------
__global__ void embed_kernel(const int* __restrict__ ques) {
    int idx = blockIdx.x * blockDim.x + threadIdx.x;
    if (idx >= Bq * Wq * Eq) return;
    int e = idx & (Eq - 1);
    int bw = idx >> 9;
    int v = ques[bw];
    g_emb[idx] = (v > 0) ? g_table[(size_t)(v - 1) * Eq + e] : 0.0f;
}

// ---------------- TF32 tensor-core NT GEMM ----------------
// C[dir] = A[dir](MxK, row-major) * Bw[dir](NxK, row-major)^T (+ bias)
// 128x128 CTA tile, BK=16, 256 threads = 8 warps (2m x 4n), warp tile 64x32,
// mma.sync.m16n8k8.tf32. Smem k-major with pad 8 -> fragment loads conflict-free.
template <int HAS_BIAS>
__global__ __launch_bounds__(256) void gemm_tf32(
    const float* __restrict__ A, size_t aDirStride,
    const float* __restrict__ Bw, size_t bDirStride,
    const float* __restrict__ bias,          // (2,2,G4): add bias[d][0][n]+bias[d][1][n]
    float* __restrict__ C, size_t cDirStride,
    int M, int N, int K)
{
    __shared__ uint32_t As[16][136];
    __shared__ uint32_t Bs[16][136];

    int dir = blockIdx.z;
    A  += (size_t)dir * aDirStride;
    Bw += (size_t)dir * bDirStride;
    C  += (size_t)dir * cDirStride;

    int m0 = blockIdx.y * 128;
    int n0 = blockIdx.x * 128;
    int tid = threadIdx.x;
    int wid = tid >> 5, lane = tid & 31;
    int wm = wid >> 2, wn = wid & 3;         // warp origin (wm*64, wn*32)
    int gid = lane >> 2, tg = lane & 3;

    int lr = tid >> 2;          // 0..63
    int lk = (tid & 3) * 4;     // 0,4,8,12

    float acc[4][4][4];
#pragma unroll
    for (int mt = 0; mt < 4; mt++)
#pragma unroll
        for (int nt = 0; nt < 4; nt++)
#pragma unroll
            for (int r = 0; r < 4; r++) acc[mt][nt][r] = 0.0f;

    for (int k0 = 0; k0 < K; k0 += 16) {
        float4 a0 = *(const float4*)(A + (size_t)(m0 + lr) * K + k0 + lk);
        float4 a1 = *(const float4*)(A + (size_t)(m0 + lr + 64) * K + k0 + lk);
        float4 b0 = *(const float4*)(Bw + (size_t)(n0 + lr) * K + k0 + lk);
        float4 b1 = *(const float4*)(Bw + (size_t)(n0 + lr + 64) * K + k0 + lk);
        __syncthreads();
        As[lk + 0][lr] = f2tf32(a0.x); As[lk + 1][lr] = f2tf32(a0.y);
        As[lk + 2][lr] = f2tf32(a0.z); As[lk + 3][lr] = f2tf32(a0.w);
        As[lk + 0][lr + 64] = f2tf32(a1.x); As[lk + 1][lr + 64] = f2tf32(a1.y);
        As[lk + 2][lr + 64] = f2tf32(a1.z); As[lk + 3][lr + 64] = f2tf32(a1.w);
        Bs[lk + 0][lr] = f2tf32(b0.x); Bs[lk + 1][lr] = f2tf32(b0.y);
        Bs[lk + 2][lr] = f2tf32(b0.z); Bs[lk + 3][lr] = f2tf32(b0.w);
        Bs[lk + 0][lr + 64] = f2tf32(b1.x); Bs[lk + 1][lr + 64] = f2tf32(b1.y);
        Bs[lk + 2][lr + 64] = f2tf32(b1.z); Bs[lk + 3][lr + 64] = f2tf32(b1.w);
        __syncthreads();

#pragma unroll
        for (int kc = 0; kc < 16; kc += 8) {
            uint32_t af[4][4], bf[4][2];
#pragma unroll
            for (int mt = 0; mt < 4; mt++) {
                int m = wm * 64 + mt * 16 + gid;
                af[mt][0] = As[kc + tg][m];
                af[mt][1] = As[kc + tg][m + 8];
                af[mt][2] = As[kc + tg + 4][m];
                af[mt][3] = As[kc + tg + 4][m + 8];
            }
#pragma unroll
            for (int nt = 0; nt < 4; nt++) {
                int n = wn * 32 + nt * 8 + gid;
                bf[nt][0] = Bs[kc + tg][n];
                bf[nt][1] = Bs[kc + tg + 4][n];
            }
#pragma unroll
            for (int mt = 0; mt < 4; mt++)
#pragma unroll
                for (int nt = 0; nt < 4; nt++) {
                    asm volatile(
                        "mma.sync.aligned.m16n8k8.row.col.f32.tf32.tf32.f32 "
                        "{%0,%1,%2,%3}, {%4,%5,%6,%7}, {%8,%9}, {%0,%1,%2,%3};"
                        : "+f"(acc[mt][nt][0]), "+f"(acc[mt][nt][1]),
                          "+f"(acc[mt][nt][2]), "+f"(acc[mt][nt][3])
                        : "r"(af[mt][0]), "r"(af[mt][1]), "r"(af[mt][2]), "r"(af[mt][3]),
                          "r"(bf[nt][0]), "r"(bf[nt][1]));
                }
        }
    }

    const float* bp = bias + (size_t)dir * 2 * G4;
#pragma unroll
    for (int mt = 0; mt < 4; mt++) {
#pragma unroll
        for (int nt = 0; nt < 4; nt++) {
            int m = m0 + wm * 64 + mt * 16 + gid;
            int n = n0 + wn * 32 + nt * 8 + tg * 2;
            float2 v0, v1;
            v0.x = acc[mt][nt][0]; v0.y = acc[mt][nt][1];
            v1.x = acc[mt][nt][2]; v1.y = acc[mt][nt][3];
            if (HAS_BIAS) {
                float bx = bp[n] + bp[G4 + n];
                float by = bp[n + 1] + bp[G4 + n + 1];
                v0.x += bx; v0.y += by; v1.x += bx; v1.y += by;
            }
            *(float2*)(C + (size_t)m * N + n) = v0;
            *(float2*)(C + (size_t)(m + 8) * N + n) = v1;
        }
    }
}

// ---------------- fused LSTM gate update (one timestep, both dirs) ----------------
__global__ void lstm_step_kernel(const float* __restrict__ xg, const float* __restrict__ gates,
                                 float* __restrict__ hseq, int step, int first)
{
    int idx = blockIdx.x * blockDim.x + threadIdx.x;
    if (idx >= 2 * Bq * Hq) return;
    int dir = idx / (Bq * Hq);
    int r = idx - dir * (Bq * Hq);
    int b = r >> 9;
    int h = r & (Hq - 1);
    int t = dir ? (Wq - 1 - step) : step;

    const float* xp = xg + (size_t)dir * Bq * Wq * G4 + ((size_t)b * Wq + t) * G4;
    float gi = xp[h];
    float gf = xp[Hq + h];
    float gg = xp[2 * Hq + h];
    float go = xp[3 * Hq + h];
    if (!first) {
        const float* gp = gates + (size_t)dir * Bq * G4 + (size_t)b * G4;
        gi += gp[h]; gf += gp[Hq + h]; gg += gp[2 * Hq + h]; go += gp[3 * Hq + h];
    }
    float cprev = first ? 0.0f : g_c[idx];
    float c = sigf(gf) * cprev + sigf(gi) * tanhf(gg);
    float hn = sigf(go) * tanhf(c);
    g_c[idx] = c;
    g_h[idx] = hn;
    hseq[((size_t)b * Wq + t) * (2 * Hq) + dir * Hq + h] = hn;
}

// ---------------- final gather at t = len-1 ----------------
__global__ void gather_kernel(const int* __restrict__ qlen, float* __restrict__ out) {
    int idx = blockIdx.x * blockDim.x + threadIdx.x;
    if (idx >= Bq * 2 * Hq) return;
    int b = idx / (2 * Hq);
    int j = idx - b * (2 * Hq);
    int t = qlen[b] - 1;
    out[idx] = g_hseq[((size_t)b * Wq + t) * (2 * Hq) + j];
}

// ---------------- launch ----------------
extern "C" void kernel_launch(void* const* d_in, const int* in_sizes, int n_in,
                              void* d_out, int out_size)
{
    const int*   ques = (const int*)d_in[0];
    const int*   qlen = (const int*)d_in[1];
    const float* lut  = (const float*)d_in[2];
    const float* wih0 = (const float*)d_in[3];
    const float* whh0 = (const float*)d_in[4];
    const float* b0   = (const float*)d_in[5];
    const float* wih1 = (const float*)d_in[6];
    const float* whh1 = (const float*)d_in[7];
    const float* b1   = (const float*)d_in[8];
    float* out = (float*)d_out;

    float *emb, *xg, *hseq, *gates, *hbuf;
    cudaGetSymbolAddress((void**)&emb,   g_emb);
    cudaGetSymbolAddress((void**)&xg,    g_xg);
    cudaGetSymbolAddress((void**)&hseq,  g_hseq);
    cudaGetSymbolAddress((void**)&gates, g_gates);
    cudaGetSymbolAddress((void**)&hbuf,  g_h);

    // 0) tanh + transpose of lookup table
    {
        dim3 grid((Vq + 31) / 32, Eq / 32);
        tanh_transpose_kernel<<<grid, dim3(32, 8)>>>(lut);
    }

    // 1) embedding
    embed_kernel<<<(Bq * Wq * Eq + 255) / 256, 256>>>(ques);

    // 2) layer-0 input projection
    {
        dim3 grid(G4 / 128, (Bq * Wq) / 128, 2);
        gemm_tf32<1><<<grid, 256>>>(emb, 0,
                                    wih0, (size_t)G4 * Eq,
                                    b0,
                                    xg, (size_t)Bq * Wq * G4,
                                    Bq * Wq, G4, Eq);
    }

    // 3) layer-0 recurrence
    for (int step = 0; step < Wq; step++) {
        if (step > 0) {
            dim3 grid(G4 / 128, Bq / 128, 2);
            gemm_tf32<0><<<grid, 256>>>(hbuf, (size_t)Bq * Hq,
                                        whh0, (size_t)G4 * Hq,
                                        b0,
                                        gates, (size_t)Bq * G4,
                                        Bq, G4, Hq);
        }
        lstm_step_kernel<<<(2 * Bq * Hq + 255) / 256, 256>>>(xg, gates, hseq, step, step == 0);
    }

    // 4) layer-1 input projection (K = 2H)
    {
        dim3 grid(G4 / 128, (Bq * Wq) / 128, 2);
        gemm_tf32<1><<<grid, 256>>>(hseq, 0,
                                    wih1, (size_t)G4 * 2 * Hq,
                                    b1,
                                    xg, (size_t)Bq * Wq * G4,
                                    Bq * Wq, G4, 2 * Hq);
    }

    // 5) layer-1 recurrence
    for (int step = 0; step < Wq; step++) {
        if (step > 0) {
            dim3 grid(G4 / 128, Bq / 128, 2);
            gemm_tf32<0><<<grid, 256>>>(hbuf, (size_t)Bq * Hq,
                                        whh1, (size_t)G4 * Hq,
                                        b1,
                                        gates, (size_t)Bq * G4,
                                        Bq, G4, Hq);
        }
        lstm_step_kernel<<<(2 * Bq * Hq + 255) / 256, 256>>>(xg, gates, hseq, step, step == 0);
    }

    // 6) gather
    gather_kernel<<<(Bq * 2 * Hq + 255) / 256, 256>>>(qlen, out);
}

// round 3
// speedup vs baseline: 1.8939x; 1.0003x over previous
#include <cuda_runtime.h>
#include <math.h>
#include <stdint.h>

#define Bq 512
#define Wq 40
#define Vq 12000
#define Eq 512
#define Hq 512
#define G4 2048   // 4*H

// ---------------- scratch (device globals; no allocation) ----------------
__device__ float g_table[(size_t)Vq * Eq];        // 24.6 MB  tanh(lut^T)
__device__ float g_emb[Bq * Wq * Eq];             // 41.9 MB
__device__ float g_xg[2 * Bq * Wq * G4];          // 335 MB
__device__ float g_hseq[Bq * Wq * 2 * Hq];        // 84 MB
__device__ float g_gates[2 * Bq * G4];            // 8.4 MB
__device__ float g_h[2 * Bq * Hq];
__device__ float g_c[2 * Bq * Hq];

__device__ __forceinline__ float sigf(float x) { return 1.0f / (1.0f + expf(-x)); }

__device__ __forceinline__ uint32_t f2tf32(float x) {
    uint32_t r;
    asm("cvt.rna.tf32.f32 %0, %1;" : "=r"(r) : "f"(x));
    return r;
}

// ---------------- tanh + transpose of lookup table: g_table[v][e] = tanh(lut[e][v]) ----
__global__ void tanh_transpose_kernel(const float* __restrict__ lut) {
    __shared__ float tile[32][33];
    int v0 = blockIdx.x * 32;
    int e0 = blockIdx.y * 32;
    int tx = threadIdx.x, ty = threadIdx.y;   // block (32, 8)
#pragma unroll
    for (int i = ty; i < 32; i += 8) {
        int e = e0 + i, v = v0 + tx;
        tile[i][tx] = (v < Vq) ? lut[(size_t)e * Vq + v] : 0.0f;
    }
    __syncthreads();
#pragma unroll
    for (int i = ty; i < 32; i += 8) {
        int v = v0 + i, e = e0 + tx;
        if (v < Vq) g_table[(size_t)v * Eq + e] = tanhf(tile[tx][i]);
    }
}

// ---------------- embedding gather (coalesced both sides) ----------------
__global__ void embed_kernel(const int* __restrict__ ques) {
    int idx = blockIdx.x * blockDim.x + threadIdx.x;
    if (idx >= Bq * Wq * Eq) return;
    int e = idx & (Eq - 1);
    int bw = idx >> 9;
    int v = ques[bw];
    g_emb[idx] = (v > 0) ? g_table[(size_t)(v - 1) * Eq + e] : 0.0f;
}

// ---------------- TF32 tensor-core NT GEMM ----------------
// C[dir] = A[dir](MxK, row-major) * Bw[dir](NxK, row-major)^T (+ bias)
// 128x128 CTA tile, BK=16, 256 threads = 8 warps (2m x 4n), warp tile 64x32,
// mma.sync.m16n8k8.tf32. Smem k-major with pad 8 -> fragment loads conflict-free.
template <int HAS_BIAS>
__global__ __launch_bounds__(256) void gemm_tf32(
    const float* __restrict__ A, size_t aDirStride,
    const float* __restrict__ Bw, size_t bDirStride,
    const float* __restrict__ bias,          // (2,2,G4): add bias[d][0][n]+bias[d][1][n]
    float* __restrict__ C, size_t cDirStride,
    int M, int N, int K)
{
    __shared__ uint32_t As[16][136];
    __shared__ uint32_t Bs[16][136];

    int dir = blockIdx.z;
    A  += (size_t)dir * aDirStride;
    Bw += (size_t)dir * bDirStride;
    C  += (size_t)dir * cDirStride;

    int m0 = blockIdx.y * 128;
    int n0 = blockIdx.x * 128;
    int tid = threadIdx.x;
    int wid = tid >> 5, lane = tid & 31;
    int wm = wid >> 2, wn = wid & 3;         // warp origin (wm*64, wn*32)
    int gid = lane >> 2, tg = lane & 3;

    int lr = tid >> 2;          // 0..63
    int lk = (tid & 3) * 4;     // 0,4,8,12

    float acc[4][4][4];
#pragma unroll
    for (int mt = 0; mt < 4; mt++)
#pragma unroll
        for (int nt = 0; nt < 4; nt++)
#pragma unroll
            for (int r = 0; r < 4; r++) acc[mt][nt][r] = 0.0f;

    for (int k0 = 0; k0 < K; k0 += 16) {
        float4 a0 = *(const float4*)(A + (size_t)(m0 + lr) * K + k0 + lk);
        float4 a1 = *(const float4*)(A + (size_t)(m0 + lr + 64) * K + k0 + lk);
        float4 b0 = *(const float4*)(Bw + (size_t)(n0 + lr) * K + k0 + lk);
        float4 b1 = *(const float4*)(Bw + (size_t)(n0 + lr + 64) * K + k0 + lk);
        __syncthreads();
        As[lk + 0][lr] = f2tf32(a0.x); As[lk + 1][lr] = f2tf32(a0.y);
        As[lk + 2][lr] = f2tf32(a0.z); As[lk + 3][lr] = f2tf32(a0.w);
        As[lk + 0][lr + 64] = f2tf32(a1.x); As[lk + 1][lr + 64] = f2tf32(a1.y);
        As[lk + 2][lr + 64] = f2tf32(a1.z); As[lk + 3][lr + 64] = f2tf32(a1.w);
        Bs[lk + 0][lr] = f2tf32(b0.x); Bs[lk + 1][lr] = f2tf32(b0.y);
        Bs[lk + 2][lr] = f2tf32(b0.z); Bs[lk + 3][lr] = f2tf32(b0.w);
        Bs[lk + 0][lr + 64] = f2tf32(b1.x); Bs[lk + 1][lr + 64] = f2tf32(b1.y);
        Bs[lk + 2][lr + 64] = f2tf32(b1.z); Bs[lk + 3][lr + 64] = f2tf32(b1.w);
        __syncthreads();

#pragma unroll
        for (int kc = 0; kc < 16; kc += 8) {
            uint32_t af[4][4], bf[4][2];
#pragma unroll
            for (int mt = 0; mt < 4; mt++) {
                int m = wm * 64 + mt * 16 + gid;
                af[mt][0] = As[kc + tg][m];
                af[mt][1] = As[kc + tg][m + 8];
                af[mt][2] = As[kc + tg + 4][m];
                af[mt][3] = As[kc + tg + 4][m + 8];
            }
#pragma unroll
            for (int nt = 0; nt < 4; nt++) {
                int n = wn * 32 + nt * 8 + gid;
                bf[nt][0] = Bs[kc + tg][n];
                bf[nt][1] = Bs[kc + tg + 4][n];
            }
#pragma unroll
            for (int mt = 0; mt < 4; mt++)
#pragma unroll
                for (int nt = 0; nt < 4; nt++) {
                    asm volatile(
                        "mma.sync.aligned.m16n8k8.row.col.f32.tf32.tf32.f32 "
                        "{%0,%1,%2,%3}, {%4,%5,%6,%7}, {%8,%9}, {%0,%1,%2,%3};"
                        : "+f"(acc[mt][nt][0]), "+f"(acc[mt][nt][1]),
                          "+f"(acc[mt][nt][2]), "+f"(acc[mt][nt][3])
                        : "r"(af[mt][0]), "r"(af[mt][1]), "r"(af[mt][2]), "r"(af[mt][3]),
                          "r"(bf[nt][0]), "r"(bf[nt][1]));
                }
        }
    }

    const float* bp = bias + (size_t)dir * 2 * G4;
#pragma unroll
    for (int mt = 0; mt < 4; mt++) {
#pragma unroll
        for (int nt = 0; nt < 4; nt++) {
            int m = m0 + wm * 64 + mt * 16 + gid;
            int n = n0 + wn * 32 + nt * 8 + tg * 2;
            float2 v0, v1;
            v0.x = acc[mt][nt][0]; v0.y = acc[mt][nt][1];
            v1.x = acc[mt][nt][2]; v1.y = acc[mt][nt][3];
            if (HAS_BIAS) {
                float bx = bp[n] + bp[G4 + n];
                float by = bp[n + 1] + bp[G4 + n + 1];
                v0.x += bx; v0.y += by; v1.x += bx; v1.y += by;
            }
            *(float2*)(C + (size_t)m * N + n) = v0;
            *(float2*)(C + (size_t)(m + 8) * N + n) = v1;
        }
    }
}

// ---------------- fused LSTM gate update (one timestep, both dirs) ----------------
__global__ void lstm_step_kernel(const float* __restrict__ xg, const float* __restrict__ gates,
                                 float* __restrict__ hseq, int step, int first)
{
    int idx = blockIdx.x * blockDim.x + threadIdx.x;
    if (idx >= 2 * Bq * Hq) return;
    int dir = idx / (Bq * Hq);
    int r = idx - dir * (Bq * Hq);
    int b = r >> 9;
    int h = r & (Hq - 1);
    int t = dir ? (Wq - 1 - step) : step;

    const float* xp = xg + (size_t)dir * Bq * Wq * G4 + ((size_t)b * Wq + t) * G4;
    float gi = xp[h];
    float gf = xp[Hq + h];
    float gg = xp[2 * Hq + h];
    float go = xp[3 * Hq + h];
    if (!first) {
        const float* gp = gates + (size_t)dir * Bq * G4 + (size_t)b * G4;
        gi += gp[h]; gf += gp[Hq + h]; gg += gp[2 * Hq + h]; go += gp[3 * Hq + h];
    }
    float cprev = first ? 0.0f : g_c[idx];
    float c = sigf(gf) * cprev + sigf(gi) * tanhf(gg);
    float hn = sigf(go) * tanhf(c);
    g_c[idx] = c;
    g_h[idx] = hn;
    hseq[((size_t)b * Wq + t) * (2 * Hq) + dir * Hq + h] = hn;
}

// ---------------- final gather at t = len-1 ----------------
__global__ void gather_kernel(const int* __restrict__ qlen, float* __restrict__ out) {
    int idx = blockIdx.x * blockDim.x + threadIdx.x;
    if (idx >= Bq * 2 * Hq) return;
    int b = idx / (2 * Hq);
    int j = idx - b * (2 * Hq);
    int t = qlen[b] - 1;
    out[idx] = g_hseq[((size_t)b * Wq + t) * (2 * Hq) + j];
}

// ---------------- launch ----------------
extern "C" void kernel_launch(void* const* d_in, const int* in_sizes, int n_in,
                              void* d_out, int out_size)
{
    const int*   ques = (const int*)d_in[0];
    const int*   qlen = (const int*)d_in[1];
    const float* lut  = (const float*)d_in[2];
    const float* wih0 = (const float*)d_in[3];
    const float* whh0 = (const float*)d_in[4];
    const float* b0   = (const float*)d_in[5];
    const float* wih1 = (const float*)d_in[6];
    const float* whh1 = (const float*)d_in[7];
    const float* b1   = (const float*)d_in[8];
    float* out = (float*)d_out;

    float *emb, *xg, *hseq, *gates, *hbuf;
    cudaGetSymbolAddress((void**)&emb,   g_emb);
    cudaGetSymbolAddress((void**)&xg,    g_xg);
    cudaGetSymbolAddress((void**)&hseq,  g_hseq);
    cudaGetSymbolAddress((void**)&gates, g_gates);
    cudaGetSymbolAddress((void**)&hbuf,  g_h);

    // 0) tanh + transpose of lookup table
    {
        dim3 grid((Vq + 31) / 32, Eq / 32);
        tanh_transpose_kernel<<<grid, dim3(32, 8)>>>(lut);
    }

    // 1) embedding
    embed_kernel<<<(Bq * Wq * Eq + 255) / 256, 256>>>(ques);

    // 2) layer-0 input projection
    {
        dim3 grid(G4 / 128, (Bq * Wq) / 128, 2);
        gemm_tf32<1><<<grid, 256>>>(emb, 0,
                                    wih0, (size_t)G4 * Eq,
                                    b0,
                                    xg, (size_t)Bq * Wq * G4,
                                    Bq * Wq, G4, Eq);
    }

    // 3) layer-0 recurrence
    for (int step = 0; step < Wq; step++) {
        if (step > 0) {
            dim3 grid(G4 / 128, Bq / 128, 2);
            gemm_tf32<0><<<grid, 256>>>(hbuf, (size_t)Bq * Hq,
                                        whh0, (size_t)G4 * Hq,
                                        b0,
                                        gates, (size_t)Bq * G4,
                                        Bq, G4, Hq);
        }
        lstm_step_kernel<<<(2 * Bq * Hq + 255) / 256, 256>>>(xg, gates, hseq, step, step == 0);
    }

    // 4) layer-1 input projection (K = 2H)
    {
        dim3 grid(G4 / 128, (Bq * Wq) / 128, 2);
        gemm_tf32<1><<<grid, 256>>>(hseq, 0,
                                    wih1, (size_t)G4 * 2 * Hq,
                                    b1,
                                    xg, (size_t)Bq * Wq * G4,
                                    Bq * Wq, G4, 2 * Hq);
    }

    // 5) layer-1 recurrence
    for (int step = 0; step < Wq; step++) {
        if (step > 0) {
            dim3 grid(G4 / 128, Bq / 128, 2);
            gemm_tf32<0><<<grid, 256>>>(hbuf, (size_t)Bq * Hq,
                                        whh1, (size_t)G4 * Hq,
                                        b1,
                                        gates, (size_t)Bq * G4,
                                        Bq, G4, Hq);
        }
        lstm_step_kernel<<<(2 * Bq * Hq + 255) / 256, 256>>>(xg, gates, hseq, step, step == 0);
    }

    // 6) gather
    gather_kernel<<<(Bq * 2 * Hq + 255) / 256, 256>>>(qlen, out);
}

// round 4
// speedup vs baseline: 2.0004x; 1.0562x over previous
#include <cuda_runtime.h>
#include <math.h>
#include <stdint.h>

#define Bq 512
#define Wq 40
#define Vq 12000
#define Eq 512
#define Hq 512
#define G4 2048   // 4*H
#define NCTA 128

// ---------------- scratch (device globals; no allocation) ----------------
__device__ float g_table[(size_t)Vq * Eq];        // tanh(lut^T)
__device__ float g_emb[Bq * Wq * Eq];
__device__ float g_xg[2 * (size_t)Bq * Wq * G4];  // per-dir input projections
__device__ float g_hseq[Bq * Wq * 2 * Hq];        // layer output sequence
__device__ uint32_t g_ha[2][2 * Bq * Hq];         // tf32 h ping-pong (GEMM A)
__device__ float g_c[2 * Bq * Hq];
__device__ uint32_t g_whh_t[2][2 * G4 * Hq];      // tf32 recurrent weights per layer
__device__ unsigned g_bar[2 * Wq];

__device__ __forceinline__ float sig_fast(float x) {
    return __fdividef(1.0f, 1.0f + __expf(-x));
}
__device__ __forceinline__ float tanh_fast(float x) {
    return 2.0f * __fdividef(1.0f, 1.0f + __expf(-2.0f * x)) - 1.0f;
}
__device__ __forceinline__ uint32_t f2tf32(float x) {
    uint32_t r;
    asm("cvt.rna.tf32.f32 %0, %1;" : "=r"(r) : "f"(x));
    return r;
}
__device__ __forceinline__ void cp16(uint32_t dst, const void* src) {
    asm volatile("cp.async.cg.shared.global [%0], [%1], 16;" :: "r"(dst), "l"(src));
}

// ---------------- one-time weight cvt to tf32 ----------------
__global__ void cvt_whh_kernel(const float* __restrict__ src, int layer) {
    int idx = blockIdx.x * blockDim.x + threadIdx.x;
    if (idx < 2 * G4 * Hq) g_whh_t[layer][idx] = f2tf32(src[idx]);
}

__global__ void zero_bar_kernel() {
    if (threadIdx.x < 2 * Wq) g_bar[threadIdx.x] = 0;
}

// ---------------- tanh + transpose lookup: g_table[v][e] = tanh(lut[e][v]) ----
__global__ void tanh_transpose_kernel(const float* __restrict__ lut) {
    __shared__ float tile[32][33];
    int v0 = blockIdx.x * 32;
    int e0 = blockIdx.y * 32;
    int tx = threadIdx.x, ty = threadIdx.y;
#pragma unroll
    for (int i = ty; i < 32; i += 8) {
        int e = e0 + i, v = v0 + tx;
        tile[i][tx] = (v < Vq) ? lut[(size_t)e * Vq + v] : 0.0f;
    }
    __syncthreads();
#pragma unroll
    for (int i = ty; i < 32; i += 8) {
        int v = v0 + i, e = e0 + tx;
        if (v < Vq) g_table[(size_t)v * Eq + e] = tanhf(tile[tx][i]);
    }
}

// ---------------- embedding gather ----------------
__global__ void embed_kernel(const int* __restrict__ ques) {
    int idx = blockIdx.x * blockDim.x + threadIdx.x;
    if (idx >= Bq * Wq * Eq) return;
    int e = idx & (Eq - 1);
    int bw = idx >> 9;
    int v = ques[bw];
    g_emb[idx] = (v > 0) ? g_table[(size_t)(v - 1) * Eq + e] : 0.0f;
}

// ---------------- TF32 tensor-core NT GEMM (input projections) ----------------
template <int HAS_BIAS>
__global__ __launch_bounds__(256) void gemm_tf32(
    const float* __restrict__ A, size_t aDirStride,
    const float* __restrict__ Bw, size_t bDirStride,
    const float* __restrict__ bias,
    float* __restrict__ C, size_t cDirStride,
    int M, int N, int K)
{
    __shared__ uint32_t As[16][136];
    __shared__ uint32_t Bs[16][136];

    int dir = blockIdx.z;
    A  += (size_t)dir * aDirStride;
    Bw += (size_t)dir * bDirStride;
    C  += (size_t)dir * cDirStride;

    int m0 = blockIdx.y * 128;
    int n0 = blockIdx.x * 128;
    int tid = threadIdx.x;
    int wid = tid >> 5, lane = tid & 31;
    int wm = wid >> 2, wn = wid & 3;
    int gid = lane >> 2, tg = lane & 3;

    int lr = tid >> 2;
    int lk = (tid & 3) * 4;

    float acc[4][4][4];
#pragma unroll
    for (int mt = 0; mt < 4; mt++)
#pragma unroll
        for (int nt = 0; nt < 4; nt++)
#pragma unroll
            for (int r = 0; r < 4; r++) acc[mt][nt][r] = 0.0f;

    for (int k0 = 0; k0 < K; k0 += 16) {
        float4 a0 = *(const float4*)(A + (size_t)(m0 + lr) * K + k0 + lk);
        float4 a1 = *(const float4*)(A + (size_t)(m0 + lr + 64) * K + k0 + lk);
        float4 b0 = *(const float4*)(Bw + (size_t)(n0 + lr) * K + k0 + lk);
        float4 b1 = *(const float4*)(Bw + (size_t)(n0 + lr + 64) * K + k0 + lk);
        __syncthreads();
        As[lk + 0][lr] = f2tf32(a0.x); As[lk + 1][lr] = f2tf32(a0.y);
        As[lk + 2][lr] = f2tf32(a0.z); As[lk + 3][lr] = f2tf32(a0.w);
        As[lk + 0][lr + 64] = f2tf32(a1.x); As[lk + 1][lr + 64] = f2tf32(a1.y);
        As[lk + 2][lr + 64] = f2tf32(a1.z); As[lk + 3][lr + 64] = f2tf32(a1.w);
        Bs[lk + 0][lr] = f2tf32(b0.x); Bs[lk + 1][lr] = f2tf32(b0.y);
        Bs[lk + 2][lr] = f2tf32(b0.z); Bs[lk + 3][lr] = f2tf32(b0.w);
        Bs[lk + 0][lr + 64] = f2tf32(b1.x); Bs[lk + 1][lr + 64] = f2tf32(b1.y);
        Bs[lk + 2][lr + 64] = f2tf32(b1.z); Bs[lk + 3][lr + 64] = f2tf32(b1.w);
        __syncthreads();

#pragma unroll
        for (int kc = 0; kc < 16; kc += 8) {
            uint32_t af[4][4], bf[4][2];
#pragma unroll
            for (int mt = 0; mt < 4; mt++) {
                int m = wm * 64 + mt * 16 + gid;
                af[mt][0] = As[kc + tg][m];
                af[mt][1] = As[kc + tg][m + 8];
                af[mt][2] = As[kc + tg + 4][m];
                af[mt][3] = As[kc + tg + 4][m + 8];
            }
#pragma unroll
            for (int nt = 0; nt < 4; nt++) {
                int n = wn * 32 + nt * 8 + gid;
                bf[nt][0] = Bs[kc + tg][n];
                bf[nt][1] = Bs[kc + tg + 4][n];
            }
#pragma unroll
            for (int mt = 0; mt < 4; mt++)
#pragma unroll
                for (int nt = 0; nt < 4; nt++) {
                    asm volatile(
                        "mma.sync.aligned.m16n8k8.row.col.f32.tf32.tf32.f32 "
                        "{%0,%1,%2,%3}, {%4,%5,%6,%7}, {%8,%9}, {%0,%1,%2,%3};"
                        : "+f"(acc[mt][nt][0]), "+f"(acc[mt][nt][1]),
                          "+f"(acc[mt][nt][2]), "+f"(acc[mt][nt][3])
                        : "r"(af[mt][0]), "r"(af[mt][1]), "r"(af[mt][2]), "r"(af[mt][3]),
                          "r"(bf[nt][0]), "r"(bf[nt][1]));
                }
        }
    }

    const float* bp = bias + (size_t)dir * 2 * G4;
#pragma unroll
    for (int mt = 0; mt < 4; mt++) {
#pragma unroll
        for (int nt = 0; nt < 4; nt++) {
            int m = m0 + wm * 64 + mt * 16 + gid;
            int n = n0 + wn * 32 + nt * 8 + tg * 2;
            float2 v0, v1;
            v0.x = acc[mt][nt][0]; v0.y = acc[mt][nt][1];
            v1.x = acc[mt][nt][2]; v1.y = acc[mt][nt][3];
            if (HAS_BIAS) {
                float bx = bp[n] + bp[G4 + n];
                float by = bp[n + 1] + bp[G4 + n + 1];
                v0.x += bx; v0.y += by; v1.x += bx; v1.y += by;
            }
            *(float2*)(C + (size_t)m * N + n) = v0;
            *(float2*)(C + (size_t)(m + 8) * N + n) = v1;
        }
    }
}

// ---------------- persistent fused LSTM recurrence (one layer, both dirs) -------
// 128 CTAs: dir(2) x m-tiles(8, 64 rows of b) x h-tiles(8, 64 cols of h).
// Per step: gates[64 x 4*64] = h_prev[64 x 512] @ whh_strips[256 x 512]^T, fused
// gate update in epilogue, grid-wide spin barrier between steps.
// Dynamic smem: As[2][64][36] u32, Bs[2][256][36] u32 = 92160 B.
__global__ __launch_bounds__(256) void lstm_persist(
    const uint32_t* __restrict__ whhT,   // [2 dirs][G4][Hq] tf32
    const float* __restrict__ xg,        // [2 dirs][Bq][Wq][G4]
    int bar_ofs)
{
    extern __shared__ uint32_t sm[];
    const int AS_STRIDE = 36;
    const int AS_BUF = 64 * AS_STRIDE;        // u32 per A buffer
    const int BS_BUF = 256 * AS_STRIDE;       // u32 per B buffer
    uint32_t* AsArr = sm;                     // [2][64][36]
    uint32_t* BsArr = sm + 2 * AS_BUF;        // [2][256][36]

    int tid = threadIdx.x;
    int bx = blockIdx.x;
    int dir = bx >> 6;
    int r = bx & 63;
    int m0 = (r >> 3) * 64;
    int ht0 = (r & 7) * 64;

    int wid = tid >> 5, lane = tid & 31;
    int wm = wid >> 2, wn = wid & 3;          // warp tile: m 32 x n 64
    int gid = lane >> 2, tg = lane & 3;

    const uint32_t* wbase = whhT + (size_t)dir * G4 * Hq;
    const float* xgd = xg + (size_t)dir * Bq * Wq * G4;

    uint32_t smem_u32;
    asm("{ .reg .u64 t; cvta.to.shared.u64 t, %1; cvt.u32.u64 %0, t; }"
        : "=r"(smem_u32) : "l"(sm));
    uint32_t AsAddr = smem_u32;
    uint32_t BsAddr = smem_u32 + 2 * AS_BUF * 4;

    for (int step = 0; step < Wq; step++) {
        float acc[2][8][4];
#pragma unroll
        for (int mt = 0; mt < 2; mt++)
#pragma unroll
            for (int t = 0; t < 8; t++)
#pragma unroll
                for (int q = 0; q < 4; q++) acc[mt][t][q] = 0.0f;

        if (step > 0) {
            const uint32_t* habase = g_ha[(step - 1) & 1] + dir * Bq * Hq;

            auto loadChunk = [&](int kc, int buf) {
                int k0 = kc * 32;
#pragma unroll
                for (int i = 0; i < 2; i++) {
                    int idx = tid + i * 256;         // 0..511
                    int row = idx >> 3, seg = idx & 7;
                    cp16(AsAddr + (buf * AS_BUF + row * AS_STRIDE + seg * 4) * 4,
                         habase + (m0 + row) * Hq + k0 + seg * 4);
                }
#pragma unroll
                for (int i = 0; i < 8; i++) {
                    int idx = tid + i * 256;         // 0..2047
                    int row = idx >> 3, seg = idx & 7;
                    int grow = ((row >> 6) << 9) + ht0 + (row & 63);  // gate*512 + h
                    cp16(BsAddr + (buf * BS_BUF + row * AS_STRIDE + seg * 4) * 4,
                         wbase + (size_t)grow * Hq + k0 + seg * 4);
                }
                asm volatile("cp.async.commit_group;");
            };

            loadChunk(0, 0);
            for (int kc = 0; kc < 16; kc++) {
                int buf = kc & 1;
                if (kc < 15) {
                    loadChunk(kc + 1, buf ^ 1);
                    asm volatile("cp.async.wait_group 1;");
                } else {
                    asm volatile("cp.async.wait_group 0;");
                }
                __syncthreads();
                const uint32_t* Asb = AsArr + buf * AS_BUF;
                const uint32_t* Bsb = BsArr + buf * BS_BUF;
#pragma unroll
                for (int kk = 0; kk < 32; kk += 8) {
                    uint32_t af[2][4], bf[8][2];
#pragma unroll
                    for (int mt = 0; mt < 2; mt++) {
                        int mr = wm * 32 + mt * 16 + gid;
                        af[mt][0] = Asb[mr * AS_STRIDE + kk + tg];
                        af[mt][1] = Asb[(mr + 8) * AS_STRIDE + kk + tg];
                        af[mt][2] = Asb[mr * AS_STRIDE + kk + tg + 4];
                        af[mt][3] = Asb[(mr + 8) * AS_STRIDE + kk + tg + 4];
                    }
#pragma unroll
                    for (int t = 0; t < 8; t++) {
                        int br = ((t >> 1) << 6) + wn * 16 + ((t & 1) << 3) + gid;
                        bf[t][0] = Bsb[br * AS_STRIDE + kk + tg];
                        bf[t][1] = Bsb[br * AS_STRIDE + kk + tg + 4];
                    }
#pragma unroll
                    for (int mt = 0; mt < 2; mt++)
#pragma unroll
                        for (int t = 0; t < 8; t++) {
                            asm volatile(
                                "mma.sync.aligned.m16n8k8.row.col.f32.tf32.tf32.f32 "
                                "{%0,%1,%2,%3}, {%4,%5,%6,%7}, {%8,%9}, {%0,%1,%2,%3};"
                                : "+f"(acc[mt][t][0]), "+f"(acc[mt][t][1]),
                                  "+f"(acc[mt][t][2]), "+f"(acc[mt][t][3])
                                : "r"(af[mt][0]), "r"(af[mt][1]), "r"(af[mt][2]), "r"(af[mt][3]),
                                  "r"(bf[t][0]), "r"(bf[t][1]));
                        }
                }
                __syncthreads();
            }
        }

        // ---- fused gate epilogue ----
        int t_ = dir ? (Wq - 1 - step) : step;
        uint32_t* haw = g_ha[step & 1] + dir * Bq * Hq;
#pragma unroll
        for (int mt = 0; mt < 2; mt++) {
#pragma unroll
            for (int rs = 0; rs < 2; rs++) {
                int m = m0 + wm * 32 + mt * 16 + gid + rs * 8;
                const float* xp = xgd + ((size_t)m * Wq + t_) * G4;
#pragma unroll
                for (int sub = 0; sub < 2; sub++) {
#pragma unroll
                    for (int cs = 0; cs < 2; cs++) {
                        int hh = ht0 + wn * 16 + sub * 8 + tg * 2 + cs;
                        int ri = rs * 2 + cs;
                        float gi = acc[mt][0 + sub][ri] + xp[hh];
                        float gf = acc[mt][2 + sub][ri] + xp[512 + hh];
                        float gg = acc[mt][4 + sub][ri] + xp[1024 + hh];
                        float go = acc[mt][6 + sub][ri] + xp[1536 + hh];
                        int ci = dir * Bq * Hq + m * Hq + hh;
                        float cprev = (step == 0) ? 0.0f : g_c[ci];
                        float c = sig_fast(gf) * cprev + sig_fast(gi) * tanh_fast(gg);
                        float hn = sig_fast(go) * tanh_fast(c);
                        g_c[ci] = c;
                        haw[m * Hq + hh] = f2tf32(hn);
                        g_hseq[((size_t)m * Wq + t_) * (2 * Hq) + dir * Hq + hh] = hn;
                    }
                }
            }
        }

        // ---- grid barrier ----
        if (step < Wq - 1) {
            __threadfence();
            __syncthreads();
            if (tid == 0) {
                unsigned* ctr = &g_bar[bar_ofs + step];
                atomicAdd(ctr, 1u);
                unsigned v;
                do {
                    asm volatile("ld.acquire.gpu.u32 %0, [%1];"
                                 : "=r"(v) : "l"(ctr) : "memory");
                    if (v < NCTA) __nanosleep(64);
                } while (v < NCTA);
            }
            __syncthreads();
        }
    }
}

// ---------------- final gather at t = len-1 ----------------
__global__ void gather_kernel(const int* __restrict__ qlen, float* __restrict__ out) {
    int idx = blockIdx.x * blockDim.x + threadIdx.x;
    if (idx >= Bq * 2 * Hq) return;
    int b = idx / (2 * Hq);
    int j = idx - b * (2 * Hq);
    int t = qlen[b] - 1;
    out[idx] = g_hseq[((size_t)b * Wq + t) * (2 * Hq) + j];
}

// ---------------- launch ----------------
extern "C" void kernel_launch(void* const* d_in, const int* in_sizes, int n_in,
                              void* d_out, int out_size)
{
    const int*   ques = (const int*)d_in[0];
    const int*   qlen = (const int*)d_in[1];
    const float* lut  = (const float*)d_in[2];
    const float* wih0 = (const float*)d_in[3];
    const float* whh0 = (const float*)d_in[4];
    const float* b0   = (const float*)d_in[5];
    const float* wih1 = (const float*)d_in[6];
    const float* whh1 = (const float*)d_in[7];
    const float* b1   = (const float*)d_in[8];
    float* out = (float*)d_out;

    float *emb, *xg, *hseq;
    uint32_t *whhT;
    cudaGetSymbolAddress((void**)&emb,  g_emb);
    cudaGetSymbolAddress((void**)&xg,   g_xg);
    cudaGetSymbolAddress((void**)&hseq, g_hseq);
    cudaGetSymbolAddress((void**)&whhT, g_whh_t);

    static int smem_set = 0;
    const int PERSIST_SMEM = (2 * 64 * 36 + 2 * 256 * 36) * 4;  // 92160
    if (!smem_set) {
        cudaFuncSetAttribute(lstm_persist,
                             cudaFuncAttributeMaxDynamicSharedMemorySize, PERSIST_SMEM);
        smem_set = 1;
    }

    // 0) reset barriers, convert recurrent weights to tf32, build table
    zero_bar_kernel<<<1, 128>>>();
    cvt_whh_kernel<<<(2 * G4 * Hq + 255) / 256, 256>>>(whh0, 0);
    cvt_whh_kernel<<<(2 * G4 * Hq + 255) / 256, 256>>>(whh1, 1);
    {
        dim3 grid((Vq + 31) / 32, Eq / 32);
        tanh_transpose_kernel<<<grid, dim3(32, 8)>>>(lut);
    }

    // 1) embedding
    embed_kernel<<<(Bq * Wq * Eq + 255) / 256, 256>>>(ques);

    // 2) layer-0 input projection
    {
        dim3 grid(G4 / 128, (Bq * Wq) / 128, 2);
        gemm_tf32<1><<<grid, 256>>>(emb, 0,
                                    wih0, (size_t)G4 * Eq,
                                    b0,
                                    xg, (size_t)Bq * Wq * G4,
                                    Bq * Wq, G4, Eq);
    }

    // 3) layer-0 recurrence (persistent, fused)
    lstm_persist<<<NCTA, 256, PERSIST_SMEM>>>(whhT, xg, 0);

    // 4) layer-1 input projection (K = 2H)
    {
        dim3 grid(G4 / 128, (Bq * Wq) / 128, 2);
        gemm_tf32<1><<<grid, 256>>>(hseq, 0,
                                    wih1, (size_t)G4 * 2 * Hq,
                                    b1,
                                    xg, (size_t)Bq * Wq * G4,
                                    Bq * Wq, G4, 2 * Hq);
    }

    // 5) layer-1 recurrence
    lstm_persist<<<NCTA, 256, PERSIST_SMEM>>>(whhT + (size_t)2 * G4 * Hq, xg, Wq);

    // 6) gather
    gather_kernel<<<(Bq * 2 * Hq + 255) / 256, 256>>>(qlen, out);
}

// round 6
// speedup vs baseline: 2.8229x; 1.4112x over previous
#include <cuda_runtime.h>
#include <math.h>
#include <stdint.h>

#define Bq 512
#define Wq 40
#define Vq 12000
#define Eq 512
#define Hq 512
#define G4 2048   // 4*H
#define NCTA 128

// ---------------- scratch (device globals; no allocation) ----------------
__device__ float g_table[(size_t)Vq * Eq];        // rounded tanh(lut^T)
__device__ float g_emb[Bq * Wq * Eq];
__device__ float g_xg[2 * (size_t)Bq * Wq * G4];  // per-dir input projections
__device__ float g_hseq[Bq * Wq * 2 * Hq];        // layer output sequence
__device__ float g_ha[2][2 * Bq * Hq];            // h ping-pong (GEMM A, rounded)
__device__ float g_c[2 * Bq * Hq];
__device__ float g_wr[10485760];                  // rounded weights: wih0|whh0|wih1|whh1
__device__ unsigned g_bar[2 * Wq];

#define OFF_WIH0 0
#define OFF_WHH0 2097152
#define OFF_WIH1 4194304
#define OFF_WHH1 8388608

__device__ __forceinline__ float sig_fast(float x) {
    return __fdividef(1.0f, 1.0f + __expf(-x));
}
__device__ __forceinline__ float tanh_fast(float x) {
    return 2.0f * __fdividef(1.0f, 1.0f + __expf(-2.0f * x)) - 1.0f;
}
// RNA-round fp32 to tf32-compatible fp32 (low 13 mantissa bits zero)
__device__ __forceinline__ float rnd_tf32(float x) {
    uint32_t r;
    asm("cvt.rna.tf32.f32 %0, %1;" : "=r"(r) : "f"(x));
    return __uint_as_float(r);
}
__device__ __forceinline__ void cp16(uint32_t dst, const void* src) {
    asm volatile("cp.async.cg.shared.global [%0], [%1], 16;" :: "r"(dst), "l"(src));
}

__global__ void zero_bar_kernel() {
    if (threadIdx.x < 2 * Wq) g_bar[threadIdx.x] = 0;
}

// ---------------- one-time weight pre-round ----------------
__global__ void round_weights_kernel(const float* __restrict__ src, int dstOff, int n) {
    int i = blockIdx.x * blockDim.x + threadIdx.x;
    if (i < n) g_wr[dstOff + i] = rnd_tf32(src[i]);
}

// ---------------- tanh + transpose lookup: g_table[v][e] = rnd(tanh(lut[e][v])) --
__global__ void tanh_transpose_kernel(const float* __restrict__ lut) {
    __shared__ float tile[32][33];
    int v0 = blockIdx.x * 32;
    int e0 = blockIdx.y * 32;
    int tx = threadIdx.x, ty = threadIdx.y;
#pragma unroll
    for (int i = ty; i < 32; i += 8) {
        int e = e0 + i, v = v0 + tx;
        tile[i][tx] = (v < Vq) ? lut[(size_t)e * Vq + v] : 0.0f;
    }
    __syncthreads();
#pragma unroll
    for (int i = ty; i < 32; i += 8) {
        int v = v0 + i, e = e0 + tx;
        if (v < Vq) g_table[(size_t)v * Eq + e] = rnd_tf32(tanhf(tile[tx][i]));
    }
}

// ---------------- embedding gather ----------------
__global__ void embed_kernel(const int* __restrict__ ques) {
    int idx = blockIdx.x * blockDim.x + threadIdx.x;
    if (idx >= Bq * Wq * Eq) return;
    int e = idx & (Eq - 1);
    int bw = idx >> 9;
    int v = ques[bw];
    g_emb[idx] = (v > 0) ? g_table[(size_t)(v - 1) * Eq + e] : 0.0f;
}

// ---------------- TF32 tensor-core NT GEMM, 4-stage cp.async pipeline ----------
// Operands are pre-rounded to tf32 grid; smem holds raw bits, mma reads top 19.
#define P_ASZ (128 * 20)
#define P_SMEM (4 * P_ASZ * 2 * 4)  // 81920 B
template <int HAS_BIAS>
__global__ __launch_bounds__(256, 2) void gemm_tf32(
    const float* __restrict__ A, size_t aDirStride,
    const float* __restrict__ Bw, size_t bDirStride,
    const float* __restrict__ bias,
    float* __restrict__ C, size_t cDirStride,
    int M, int N, int K)
{
    extern __shared__ uint32_t sm[];
    uint32_t* smA = sm;                 // [4][128][20]
    uint32_t* smB = sm + 4 * P_ASZ;
    uint32_t baseA = (uint32_t)__cvta_generic_to_shared(smA);
    uint32_t baseB = (uint32_t)__cvta_generic_to_shared(smB);

    int dir = blockIdx.z;
    A  += (size_t)dir * aDirStride;
    Bw += (size_t)dir * bDirStride;
    C  += (size_t)dir * cDirStride;

    int m0 = blockIdx.y * 128;
    int n0 = blockIdx.x * 128;
    int tid = threadIdx.x;
    int wid = tid >> 5, lane = tid & 31;
    int wm = wid >> 2, wn = wid & 3;
    int gid = lane >> 2, tg = lane & 3;

    float acc[4][4][4];
#pragma unroll
    for (int mt = 0; mt < 4; mt++)
#pragma unroll
        for (int nt = 0; nt < 4; nt++)
#pragma unroll
            for (int r = 0; r < 4; r++) acc[mt][nt][r] = 0.0f;

    int niter = K >> 4;

    auto load_stage = [&](int s, int k0) {
#pragma unroll
        for (int i = 0; i < 2; i++) {
            int c = tid + i * 256;
            int row = c >> 2, seg = c & 3;
            cp16(baseA + (s * P_ASZ + row * 20 + seg * 4) * 4,
                 A + (size_t)(m0 + row) * K + k0 + seg * 4);
            cp16(baseB + (s * P_ASZ + row * 20 + seg * 4) * 4,
                 Bw + (size_t)(n0 + row) * K + k0 + seg * 4);
        }
        asm volatile("cp.async.commit_group;");
    };

    load_stage(0, 0);
    load_stage(1, 16);
    load_stage(2, 32);

    for (int it = 0; it < niter; it++) {
        int rem = niter - 1 - it;
        if (rem >= 2)      asm volatile("cp.async.wait_group 2;");
        else if (rem == 1) asm volatile("cp.async.wait_group 1;");
        else               asm volatile("cp.async.wait_group 0;");
        __syncthreads();
        if (it + 3 < niter) load_stage((it + 3) & 3, (it + 3) * 16);

        const uint32_t* Asb = smA + (it & 3) * P_ASZ;
        const uint32_t* Bsb = smB + (it & 3) * P_ASZ;
#pragma unroll
        for (int kk = 0; kk < 16; kk += 8) {
            uint32_t af[4][4], bf[4][2];
#pragma unroll
            for (int mt = 0; mt < 4; mt++) {
                int m = wm * 64 + mt * 16 + gid;
                af[mt][0] = Asb[m * 20 + kk + tg];
                af[mt][1] = Asb[(m + 8) * 20 + kk + tg];
                af[mt][2] = Asb[m * 20 + kk + tg + 4];
                af[mt][3] = Asb[(m + 8) * 20 + kk + tg + 4];
            }
#pragma unroll
            for (int nt = 0; nt < 4; nt++) {
                int n = wn * 32 + nt * 8 + gid;
                bf[nt][0] = Bsb[n * 20 + kk + tg];
                bf[nt][1] = Bsb[n * 20 + kk + tg + 4];
            }
#pragma unroll
            for (int mt = 0; mt < 4; mt++)
#pragma unroll
                for (int nt = 0; nt < 4; nt++) {
                    asm volatile(
                        "mma.sync.aligned.m16n8k8.row.col.f32.tf32.tf32.f32 "
                        "{%0,%1,%2,%3}, {%4,%5,%6,%7}, {%8,%9}, {%0,%1,%2,%3};"
                        : "+f"(acc[mt][nt][0]), "+f"(acc[mt][nt][1]),
                          "+f"(acc[mt][nt][2]), "+f"(acc[mt][nt][3])
                        : "r"(af[mt][0]), "r"(af[mt][1]), "r"(af[mt][2]), "r"(af[mt][3]),
                          "r"(bf[nt][0]), "r"(bf[nt][1]));
                }
        }
        __syncthreads();
    }

    const float* bp = bias + (size_t)dir * 2 * G4;
#pragma unroll
    for (int mt = 0; mt < 4; mt++) {
#pragma unroll
        for (int nt = 0; nt < 4; nt++) {
            int m = m0 + wm * 64 + mt * 16 + gid;
            int n = n0 + wn * 32 + nt * 8 + tg * 2;
            float2 v0, v1;
            v0.x = acc[mt][nt][0]; v0.y = acc[mt][nt][1];
            v1.x = acc[mt][nt][2]; v1.y = acc[mt][nt][3];
            if (HAS_BIAS) {
                float bx = bp[n] + bp[G4 + n];
                float by = bp[n + 1] + bp[G4 + n + 1];
                v0.x += bx; v0.y += by; v1.x += bx; v1.y += by;
            }
            *(float2*)(C + (size_t)m * N + n) = v0;
            *(float2*)(C + (size_t)(m + 8) * N + n) = v1;
        }
    }
}

// ---------------- persistent fused LSTM recurrence (one layer, both dirs) -------
// ROUND_HSEQ=1: hseq written rounded (it feeds the next GEMM as A).
// ROUND_HSEQ=0: hseq written full fp32 (it feeds the final gather).
#define R_ASZ (64 * 36)
#define R_BSZ (256 * 36)
#define R_SMEM (3 * (R_ASZ + R_BSZ) * 4)   // 138240 B
#define GSM_STRIDE 258
template <int ROUND_HSEQ>
__global__ __launch_bounds__(256) void lstm_persist(
    const float* __restrict__ whh,       // [2 dirs][G4][Hq] pre-rounded
    const float* __restrict__ xg,        // [2 dirs][Bq][Wq][G4]
    int bar_ofs)
{
    extern __shared__ uint32_t sm[];
    uint32_t* smA = sm;                   // [3][64][36]
    uint32_t* smB = sm + 3 * R_ASZ;       // [3][256][36]
    float* gsm = (float*)sm;              // epilogue alias [64][258]
    uint32_t baseA = (uint32_t)__cvta_generic_to_shared(smA);
    uint32_t baseB = (uint32_t)__cvta_generic_to_shared(smB);

    int tid = threadIdx.x;
    int bx = blockIdx.x;
    int dir = bx >> 6;
    int r = bx & 63;
    int m0 = (r >> 3) * 64;
    int ht0 = (r & 7) * 64;

    int wid = tid >> 5, lane = tid & 31;
    int wm = wid >> 2, wn = wid & 3;      // warp tile: 32 m x 64 n
    int gid = lane >> 2, tg = lane & 3;

    const float* wbase = whh + (size_t)dir * G4 * Hq;
    const float* xgd = xg + (size_t)dir * Bq * Wq * G4;

    for (int step = 0; step < Wq; step++) {
        float acc[2][8][4];
#pragma unroll
        for (int mt = 0; mt < 2; mt++)
#pragma unroll
            for (int t = 0; t < 8; t++)
#pragma unroll
                for (int q = 0; q < 4; q++) acc[mt][t][q] = 0.0f;

        if (step > 0) {
            const float* habase = g_ha[(step - 1) & 1] + dir * Bq * Hq;

            auto load_stage = [&](int s, int k0) {
#pragma unroll
                for (int i = 0; i < 2; i++) {
                    int c = tid + i * 256;
                    int row = c >> 3, seg = c & 7;
                    cp16(baseA + (s * R_ASZ + row * 36 + seg * 4) * 4,
                         habase + (size_t)(m0 + row) * Hq + k0 + seg * 4);
                }
#pragma unroll
                for (int i = 0; i < 8; i++) {
                    int c = tid + i * 256;
                    int row = c >> 3, seg = c & 7;
                    int grow = ((row >> 6) << 9) + ht0 + (row & 63);
                    cp16(baseB + (s * R_BSZ + row * 36 + seg * 4) * 4,
                         wbase + (size_t)grow * Hq + k0 + seg * 4);
                }
                asm volatile("cp.async.commit_group;");
            };

            load_stage(0, 0);
            load_stage(1, 32);

            for (int kc = 0; kc < 16; kc++) {
                if (kc < 15) asm volatile("cp.async.wait_group 1;");
                else         asm volatile("cp.async.wait_group 0;");
                __syncthreads();
                if (kc + 2 < 16) load_stage((kc + 2) % 3, (kc + 2) * 32);

                const uint32_t* Asb = smA + (kc % 3) * R_ASZ;
                const uint32_t* Bsb = smB + (kc % 3) * R_BSZ;
#pragma unroll
                for (int kk = 0; kk < 32; kk += 8) {
                    uint32_t af[2][4], bf[8][2];
#pragma unroll
                    for (int mt = 0; mt < 2; mt++) {
                        int mr = wm * 32 + mt * 16 + gid;
                        af[mt][0] = Asb[mr * 36 + kk + tg];
                        af[mt][1] = Asb[(mr + 8) * 36 + kk + tg];
                        af[mt][2] = Asb[mr * 36 + kk + tg + 4];
                        af[mt][3] = Asb[(mr + 8) * 36 + kk + tg + 4];
                    }
#pragma unroll
                    for (int t = 0; t < 8; t++) {
                        int br = ((t >> 1) << 6) + wn * 16 + ((t & 1) << 3) + gid;
                        bf[t][0] = Bsb[br * 36 + kk + tg];
                        bf[t][1] = Bsb[br * 36 + kk + tg + 4];
                    }
#pragma unroll
                    for (int mt = 0; mt < 2; mt++)
#pragma unroll
                        for (int t = 0; t < 8; t++) {
                            asm volatile(
                                "mma.sync.aligned.m16n8k8.row.col.f32.tf32.tf32.f32 "
                                "{%0,%1,%2,%3}, {%4,%5,%6,%7}, {%8,%9}, {%0,%1,%2,%3};"
                                : "+f"(acc[mt][t][0]), "+f"(acc[mt][t][1]),
                                  "+f"(acc[mt][t][2]), "+f"(acc[mt][t][3])
                                : "r"(af[mt][0]), "r"(af[mt][1]), "r"(af[mt][2]), "r"(af[mt][3]),
                                  "r"(bf[t][0]), "r"(bf[t][1]));
                        }
                }
                __syncthreads();
            }
        }

        // ---- stage gates into smem (reuses pipeline buffers) ----
        __syncthreads();
#pragma unroll
        for (int mt = 0; mt < 2; mt++)
#pragma unroll
            for (int t = 0; t < 8; t++)
#pragma unroll
                for (int rs = 0; rs < 2; rs++) {
                    int mr = wm * 32 + mt * 16 + gid + rs * 8;
                    int nc = ((t >> 1) << 6) + wn * 16 + ((t & 1) << 3) + tg * 2;
                    float2 v;
                    v.x = acc[mt][t][rs * 2];
                    v.y = acc[mt][t][rs * 2 + 1];
                    *(float2*)&gsm[mr * GSM_STRIDE + nc] = v;
                }
        __syncthreads();

        // ---- coalesced fused gate epilogue ----
        int t_ = dir ? (Wq - 1 - step) : step;
        float* haw = g_ha[step & 1] + dir * Bq * Hq;
        int hl = (tid & 31) * 2;
        int mb = tid >> 5;
#pragma unroll
        for (int mm = 0; mm < 8; mm++) {
            int m = mb + mm * 8;
            int gm = m0 + m;
            const float* gr = &gsm[m * GSM_STRIDE];
            const float* xp = xgd + ((size_t)gm * Wq + t_) * G4 + ht0 + hl;
            float2 gi = *(const float2*)&gr[hl];
            float2 gf = *(const float2*)&gr[64 + hl];
            float2 gg = *(const float2*)&gr[128 + hl];
            float2 go = *(const float2*)&gr[192 + hl];
            float2 xi = *(const float2*)&xp[0];
            float2 xf = *(const float2*)&xp[512];
            float2 xgg = *(const float2*)&xp[1024];
            float2 xo = *(const float2*)&xp[1536];
            int ci = dir * Bq * Hq + gm * Hq + ht0 + hl;
            float2 cprev = (step == 0) ? make_float2(0.f, 0.f) : *(const float2*)&g_c[ci];
            float2 cv, hv;
            cv.x = sig_fast(gf.x + xf.x) * cprev.x + sig_fast(gi.x + xi.x) * tanh_fast(gg.x + xgg.x);
            cv.y = sig_fast(gf.y + xf.y) * cprev.y + sig_fast(gi.y + xi.y) * tanh_fast(gg.y + xgg.y);
            hv.x = sig_fast(go.x + xo.x) * tanh_fast(cv.x);
            hv.y = sig_fast(go.y + xo.y) * tanh_fast(cv.y);
            *(float2*)&g_c[ci] = cv;
            float2 hr;
            hr.x = rnd_tf32(hv.x);
            hr.y = rnd_tf32(hv.y);
            *(float2*)&haw[gm * Hq + ht0 + hl] = hr;
            float2 hs = ROUND_HSEQ ? hr : hv;
            *(float2*)&g_hseq[((size_t)gm * Wq + t_) * (2 * Hq) + dir * Hq + ht0 + hl] = hs;
        }

        // ---- grid barrier ----
        if (step < Wq - 1) {
            __threadfence();
            __syncthreads();
            if (tid == 0) {
                unsigned* ctr = &g_bar[bar_ofs + step];
                atomicAdd(ctr, 1u);
                unsigned v;
                do {
                    asm volatile("ld.acquire.gpu.u32 %0, [%1];"
                                 : "=r"(v) : "l"(ctr) : "memory");
                    if (v < NCTA) __nanosleep(64);
                } while (v < NCTA);
            }
            __syncthreads();
        }
    }
}

// ---------------- final gather at t = len-1 ----------------
__global__ void gather_kernel(const int* __restrict__ qlen, float* __restrict__ out) {
    int idx = blockIdx.x * blockDim.x + threadIdx.x;
    if (idx >= Bq * 2 * Hq) return;
    int b = idx / (2 * Hq);
    int j = idx - b * (2 * Hq);
    int t = qlen[b] - 1;
    out[idx] = g_hseq[((size_t)b * Wq + t) * (2 * Hq) + j];
}

// ---------------- launch ----------------
extern "C" void kernel_launch(void* const* d_in, const int* in_sizes, int n_in,
                              void* d_out, int out_size)
{
    const int*   ques = (const int*)d_in[0];
    const int*   qlen = (const int*)d_in[1];
    const float* lut  = (const float*)d_in[2];
    const float* wih0 = (const float*)d_in[3];
    const float* whh0 = (const float*)d_in[4];
    const float* b0   = (const float*)d_in[5];
    const float* wih1 = (const float*)d_in[6];
    const float* whh1 = (const float*)d_in[7];
    const float* b1   = (const float*)d_in[8];
    float* out = (float*)d_out;

    float *emb, *xg, *hseq, *wr;
    cudaGetSymbolAddress((void**)&emb,  g_emb);
    cudaGetSymbolAddress((void**)&xg,   g_xg);
    cudaGetSymbolAddress((void**)&hseq, g_hseq);
    cudaGetSymbolAddress((void**)&wr,   g_wr);

    cudaFuncSetAttribute(gemm_tf32<1>, cudaFuncAttributeMaxDynamicSharedMemorySize, P_SMEM);
    cudaFuncSetAttribute(lstm_persist<0>, cudaFuncAttributeMaxDynamicSharedMemorySize, R_SMEM);
    cudaFuncSetAttribute(lstm_persist<1>, cudaFuncAttributeMaxDynamicSharedMemorySize, R_SMEM);

    // 0) barriers + pre-rounded weights + table
    zero_bar_kernel<<<1, 128>>>();
    round_weights_kernel<<<(2097152 + 255) / 256, 256>>>(wih0, OFF_WIH0, 2097152);
    round_weights_kernel<<<(2097152 + 255) / 256, 256>>>(whh0, OFF_WHH0, 2097152);
    round_weights_kernel<<<(4194304 + 255) / 256, 256>>>(wih1, OFF_WIH1, 4194304);
    round_weights_kernel<<<(2097152 + 255) / 256, 256>>>(whh1, OFF_WHH1, 2097152);
    {
        dim3 grid((Vq + 31) / 32, Eq / 32);
        tanh_transpose_kernel<<<grid, dim3(32, 8)>>>(lut);
    }

    // 1) embedding
    embed_kernel<<<(Bq * Wq * Eq + 255) / 256, 256>>>(ques);

    // 2) layer-0 input projection
    {
        dim3 grid(G4 / 128, (Bq * Wq) / 128, 2);
        gemm_tf32<1><<<grid, 256, P_SMEM>>>(emb, 0,
                                            wr + OFF_WIH0, (size_t)G4 * Eq,
                                            b0,
                                            xg, (size_t)Bq * Wq * G4,
                                            Bq * Wq, G4, Eq);
    }

    // 3) layer-0 recurrence (hseq rounded -> feeds layer-1 GEMM)
    lstm_persist<1><<<NCTA, 256, R_SMEM>>>(wr + OFF_WHH0, xg, 0);

    // 4) layer-1 input projection (K = 2H)
    {
        dim3 grid(G4 / 128, (Bq * Wq) / 128, 2);
        gemm_tf32<1><<<grid, 256, P_SMEM>>>(hseq, 0,
                                            wr + OFF_WIH1, (size_t)G4 * 2 * Hq,
                                            b1,
                                            xg, (size_t)Bq * Wq * G4,
                                            Bq * Wq, G4, 2 * Hq);
    }

    // 5) layer-1 recurrence (hseq full fp32 -> feeds gather)
    lstm_persist<0><<<NCTA, 256, R_SMEM>>>(wr + OFF_WHH1, xg, Wq);

    // 6) gather
    gather_kernel<<<(Bq * 2 * Hq + 255) / 256, 256>>>(qlen, out);
}